// round 1
// baseline (speedup 1.0000x reference)
#include <cuda_runtime.h>
#include <cstdint>

// Problem constants (fixed shapes per reference)
#define N_NODES 50000
#define R_REL   16
#define B_BASES 8
#define DIN     128
#define DOUT    128
#define NNZ     1600000

// Scratch: device globals (no allocation allowed)
__device__ float g_W[R_REL * DIN * DOUT];                        // 1 MB
__device__ float g_FW[(size_t)R_REL * N_NODES * DOUT];           // 409.6 MB
__device__ int   g_idx64;                                        // 1 if indices are int64

// ---------------------------------------------------------------------------
// Detect whether A_rows is int64 or int32. Row values are in [0, 50000), so if
// the buffer is int64 the odd 32-bit words are all zero; if int32 they are
// random row ids (P(all 64 are 0) ~ (1/50000)^64 = never).
// ---------------------------------------------------------------------------
__global__ void detect_dtype_kernel(const unsigned int* __restrict__ rows_raw) {
    bool all_hi_zero = true;
    for (int i = 0; i < 64; i++) {
        if (rows_raw[2 * i + 1] != 0u) { all_hi_zero = false; break; }
    }
    g_idx64 = all_hi_zero ? 1 : 0;
}

// ---------------------------------------------------------------------------
// Zero the output (harness poisons it with 0xAA).
// ---------------------------------------------------------------------------
__global__ void zero_out_kernel(float4* __restrict__ out, int n4) {
    int i = blockIdx.x * blockDim.x + threadIdx.x;
    if (i < n4) out[i] = make_float4(0.f, 0.f, 0.f, 0.f);
}

// ---------------------------------------------------------------------------
// W[r] = sum_b comp[r,b] * basis[b]   -> g_W  (R, DIN, DOUT) row-major
// ---------------------------------------------------------------------------
__global__ void compute_W_kernel(const float* __restrict__ basis,
                                 const float* __restrict__ comp) {
    int idx = blockIdx.x * blockDim.x + threadIdx.x;
    if (idx >= R_REL * DIN * DOUT) return;
    int r  = idx / (DIN * DOUT);
    int ij = idx % (DIN * DOUT);
    float acc = 0.f;
#pragma unroll
    for (int b = 0; b < B_BASES; b++)
        acc += comp[r * B_BASES + b] * basis[b * DIN * DOUT + ij];
    g_W[idx] = acc;
}

// ---------------------------------------------------------------------------
// FW[r] = X (N x 128) @ W[r] (128 x 128), written to g_FW.
// Classic register-blocked SGEMM: BM=BN=128, BK=8, TM=TN=8, 256 threads.
// grid = (ceil(N/128), R)
// ---------------------------------------------------------------------------
__global__ __launch_bounds__(256, 2)
void gemm_kernel(const float* __restrict__ X) {
    const int r  = blockIdx.y;
    const int m0 = blockIdx.x * 128;
    const float* __restrict__ W = g_W + (size_t)r * DIN * DOUT;
    float* __restrict__ C = g_FW + ((size_t)r * N_NODES + m0) * DOUT;

    __shared__ float Xs[8][128];   // [k][m]
    __shared__ float Ws[8][128];   // [k][n]

    const int tid = threadIdx.x;
    const int tx = tid % 16;             // col group (8 cols each)
    const int ty = tid / 16;             // row group (8 rows each)
    const int rowBase = ty * 8;
    const int colBase = tx * 8;

    // loader indices
    const int lrow = tid / 2;            // 0..127  (X tile row)
    const int lk   = (tid % 2) * 4;      // 0 or 4  (X tile k offset)
    const int wk   = tid / 32;           // 0..7    (W tile k)
    const int wj   = (tid % 32) * 4;     // 0..124  (W tile col)

    float acc[8][8];
#pragma unroll
    for (int i = 0; i < 8; i++)
#pragma unroll
        for (int j = 0; j < 8; j++) acc[i][j] = 0.f;

    for (int k0 = 0; k0 < DIN; k0 += 8) {
        // X tile: rows m0+lrow, k = k0+lk..+3  (transposed store into Xs)
        float4 xv = make_float4(0.f, 0.f, 0.f, 0.f);
        const int gm = m0 + lrow;
        if (gm < N_NODES)
            xv = *(const float4*)(X + (size_t)gm * DIN + k0 + lk);
        Xs[lk + 0][lrow] = xv.x;
        Xs[lk + 1][lrow] = xv.y;
        Xs[lk + 2][lrow] = xv.z;
        Xs[lk + 3][lrow] = xv.w;
        // W tile
        *(float4*)&Ws[wk][wj] = *(const float4*)(W + (size_t)(k0 + wk) * DOUT + wj);
        __syncthreads();

#pragma unroll
        for (int kk = 0; kk < 8; kk++) {
            float a[8], b[8];
            *(float4*)&a[0] = *(const float4*)&Xs[kk][rowBase];
            *(float4*)&a[4] = *(const float4*)&Xs[kk][rowBase + 4];
            *(float4*)&b[0] = *(const float4*)&Ws[kk][colBase];
            *(float4*)&b[4] = *(const float4*)&Ws[kk][colBase + 4];
#pragma unroll
            for (int i = 0; i < 8; i++)
#pragma unroll
                for (int j = 0; j < 8; j++)
                    acc[i][j] += a[i] * b[j];
        }
        __syncthreads();
    }

#pragma unroll
    for (int i = 0; i < 8; i++) {
        const int gm = m0 + rowBase + i;
        if (gm < N_NODES) {
            float* cp = C + (size_t)(rowBase + i) * DOUT + colBase;
            *(float4*)cp       = make_float4(acc[i][0], acc[i][1], acc[i][2], acc[i][3]);
            *(float4*)(cp + 4) = make_float4(acc[i][4], acc[i][5], acc[i][6], acc[i][7]);
        }
    }
}

// ---------------------------------------------------------------------------
// Scatter: out[row] += val * FW[col]  (one warp per edge, float4 per lane,
// vectorized red.global.add.v4.f32)
// ---------------------------------------------------------------------------
__global__ void scatter_kernel(const void* __restrict__ rows,
                               const void* __restrict__ cols,
                               const float* __restrict__ vals,
                               float* __restrict__ out) {
    const int lane = threadIdx.x & 31;
    const int e = (blockIdx.x * blockDim.x + threadIdx.x) >> 5;
    if (e >= NNZ) return;

    long long col, row;
    if (g_idx64) {
        col = ((const long long*)cols)[e];
        row = ((const long long*)rows)[e];
    } else {
        col = ((const int*)cols)[e];
        row = ((const int*)rows)[e];
    }
    const float v = vals[e];

    float4 d = *((const float4*)(g_FW + (size_t)col * DOUT) + lane);
    d.x *= v; d.y *= v; d.z *= v; d.w *= v;

    float* dst = out + (size_t)row * DOUT + lane * 4;
    asm volatile("red.global.add.v4.f32 [%0], {%1, %2, %3, %4};"
                 :: "l"(dst), "f"(d.x), "f"(d.y), "f"(d.z), "f"(d.w)
                 : "memory");
}

// ---------------------------------------------------------------------------
extern "C" void kernel_launch(void* const* d_in, const int* in_sizes, int n_in,
                              void* d_out, int out_size) {
    const float* X      = (const float*)d_in[0];
    const void*  A_rows = d_in[1];
    const void*  A_cols = d_in[2];
    const float* A_vals = (const float*)d_in[3];
    const float* basis  = (const float*)d_in[4];
    const float* comp   = (const float*)d_in[5];
    float* out = (float*)d_out;

    detect_dtype_kernel<<<1, 1>>>((const unsigned int*)A_rows);

    const int n4 = (N_NODES * DOUT) / 4;
    zero_out_kernel<<<(n4 + 255) / 256, 256>>>((float4*)out, n4);

    compute_W_kernel<<<(R_REL * DIN * DOUT + 255) / 256, 256>>>(basis, comp);

    dim3 ggrid((N_NODES + 127) / 128, R_REL);
    gemm_kernel<<<ggrid, 256>>>(X);

    // one warp per edge -> NNZ*32 threads
    const long long sthreads = (long long)NNZ * 32;
    scatter_kernel<<<(unsigned)((sthreads + 255) / 256), 256>>>(A_rows, A_cols, A_vals, out);
}

// round 3
// speedup vs baseline: 1.3889x; 1.3889x over previous
#include <cuda_runtime.h>
#include <cuda_bf16.h>
#include <cstdint>

// Problem constants (fixed shapes per reference)
#define N_NODES 50000
#define R_REL   16
#define B_BASES 8
#define DIN     128
#define DOUT    128
#define NNZ     1600000

#define BM 128
#define BK 16
#define M_TILES 391   // ceil(50000/128)

typedef unsigned long long ull;

// Scratch: device globals (no allocation allowed)
__device__ float g_XB[(size_t)B_BASES * N_NODES * DOUT];   // 204.8 MB
__device__ float g_FW[(size_t)R_REL * N_NODES * DOUT];     // 409.6 MB
__device__ int   g_idx64;

// ---------------------------------------------------------------------------
// f32x2 packed helpers (PTX-only path; doubles fp32 FMA throughput)
// ---------------------------------------------------------------------------
__device__ __forceinline__ ull fma2(ull a, ull b, ull c) {
    ull d;
    asm("fma.rn.f32x2 %0, %1, %2, %3;" : "=l"(d) : "l"(a), "l"(b), "l"(c));
    return d;
}
__device__ __forceinline__ ull dup2(float a) {
    ull d;
    unsigned int ai = __float_as_uint(a);
    asm("mov.b64 %0, {%1, %1};" : "=l"(d) : "r"(ai));
    return d;
}

// ---------------------------------------------------------------------------
// Detect whether indices are int64 or int32 (JAX x64 on/off). Rows < 50000,
// so for int64 the high 32-bit words are all zero.
// ---------------------------------------------------------------------------
__global__ void detect_dtype_kernel(const unsigned int* __restrict__ rows_raw) {
    bool all_hi_zero = true;
    for (int i = 0; i < 64; i++)
        if (rows_raw[2 * i + 1] != 0u) { all_hi_zero = false; break; }
    g_idx64 = all_hi_zero ? 1 : 0;
}

__global__ void zero_out_kernel(float4* __restrict__ out, int n4) {
    int i = blockIdx.x * blockDim.x + threadIdx.x;
    if (i < n4) out[i] = make_float4(0.f, 0.f, 0.f, 0.f);
}

// ---------------------------------------------------------------------------
// XB[b] = X (N x 128) @ basis[b] (128 x 128), all fp32, f32x2 accumulators.
// BM=128, BN=128 (one basis per blockIdx.y), BK=16, 256 threads, TM=8, TN=8.
// ---------------------------------------------------------------------------
__global__ __launch_bounds__(256, 2)
void gemm_xb_kernel(const float* __restrict__ X, const float* __restrict__ basis) {
    const int b  = blockIdx.y;
    const int m0 = blockIdx.x * BM;

    __shared__ float Xs[BK][BM];    // [k][m] (transposed)
    __shared__ float Bs[BK][DOUT];  // [k][n]

    const int tid = threadIdx.x;
    const int tx = tid & 15;             // col group (8 cols)
    const int ty = tid >> 4;             // row group (8 rows)
    const int rowBase = ty * 8;
    const int colBase = tx * 8;

    const float* __restrict__ Bsrc = basis + (size_t)b * DIN * DOUT;

    ull acc[8][4];
#pragma unroll
    for (int i = 0; i < 8; i++)
#pragma unroll
        for (int j = 0; j < 4; j++) acc[i][j] = 0ull;

    for (int k0 = 0; k0 < DIN; k0 += BK) {
        // X tile: 128 rows x 16 k = 512 float4; 2 per thread (transposed store)
#pragma unroll
        for (int i = 0; i < 2; i++) {
            const int f    = tid * 2 + i;
            const int lrow = f >> 2;           // 0..127
            const int lk   = (f & 3) * 4;      // 0,4,8,12
            float4 xv = make_float4(0.f, 0.f, 0.f, 0.f);
            const int gm = m0 + lrow;
            if (gm < N_NODES)
                xv = *(const float4*)(X + (size_t)gm * DIN + k0 + lk);
            Xs[lk + 0][lrow] = xv.x;
            Xs[lk + 1][lrow] = xv.y;
            Xs[lk + 2][lrow] = xv.z;
            Xs[lk + 3][lrow] = xv.w;
        }
        // B tile: 16 k x 128 n = 512 float4; 2 per thread
#pragma unroll
        for (int i = 0; i < 2; i++) {
            const int f  = tid * 2 + i;
            const int bk = f >> 5;             // 0..15
            const int bd = (f & 31) * 4;       // 0..124
            *(float4*)&Bs[bk][bd] = *(const float4*)(Bsrc + (size_t)(k0 + bk) * DOUT + bd);
        }
        __syncthreads();

#pragma unroll
        for (int kk = 0; kk < BK; kk++) {
            float a[8];
            *(float4*)&a[0] = *(const float4*)&Xs[kk][rowBase];
            *(float4*)&a[4] = *(const float4*)&Xs[kk][rowBase + 4];
            ull bp[4];
            bp[0] = *(const ull*)&Bs[kk][colBase + 0];
            bp[1] = *(const ull*)&Bs[kk][colBase + 2];
            bp[2] = *(const ull*)&Bs[kk][colBase + 4];
            bp[3] = *(const ull*)&Bs[kk][colBase + 6];
#pragma unroll
            for (int i = 0; i < 8; i++) {
                ull ad = dup2(a[i]);
#pragma unroll
                for (int j = 0; j < 4; j++)
                    acc[i][j] = fma2(ad, bp[j], acc[i][j]);
            }
        }
        __syncthreads();
    }

    // store: XB[b][m][d]
    float* outBase = g_XB + ((size_t)b * N_NODES + m0) * DOUT;
#pragma unroll
    for (int i = 0; i < 8; i++) {
        const int gm = m0 + rowBase + i;
        if (gm < N_NODES) {
            float* cp = outBase + (size_t)(rowBase + i) * DOUT + colBase;
            float4 o0, o1;
            o0.x = __uint_as_float((unsigned int)acc[i][0]);
            o0.y = __uint_as_float((unsigned int)(acc[i][0] >> 32));
            o0.z = __uint_as_float((unsigned int)acc[i][1]);
            o0.w = __uint_as_float((unsigned int)(acc[i][1] >> 32));
            o1.x = __uint_as_float((unsigned int)acc[i][2]);
            o1.y = __uint_as_float((unsigned int)(acc[i][2] >> 32));
            o1.z = __uint_as_float((unsigned int)acc[i][3]);
            o1.w = __uint_as_float((unsigned int)(acc[i][3] >> 32));
            *(float4*)cp       = o0;
            *(float4*)(cp + 4) = o1;
        }
    }
}

// ---------------------------------------------------------------------------
// FW[r][n][d] = sum_b comp[r][b] * XB[b][n][d]
// One thread per (n, d4): reads 8 float4, writes 16 float4. Memory-bound.
// ---------------------------------------------------------------------------
__global__ __launch_bounds__(256)
void combine_kernel(const float* __restrict__ comp) {
    __shared__ float cs[R_REL * B_BASES];
    if (threadIdx.x < R_REL * B_BASES) cs[threadIdx.x] = comp[threadIdx.x];
    __syncthreads();

    const int id = blockIdx.x * blockDim.x + threadIdx.x;
    if (id >= N_NODES * 32) return;
    const int n  = id >> 5;
    const int d4 = (id & 31) * 4;

    float4 xb[8];
#pragma unroll
    for (int b = 0; b < B_BASES; b++)
        xb[b] = *(const float4*)(g_XB + ((size_t)b * N_NODES + n) * DOUT + d4);

#pragma unroll
    for (int r = 0; r < R_REL; r++) {
        float4 o = make_float4(0.f, 0.f, 0.f, 0.f);
#pragma unroll
        for (int b = 0; b < B_BASES; b++) {
            const float c = cs[r * B_BASES + b];
            o.x += c * xb[b].x;
            o.y += c * xb[b].y;
            o.z += c * xb[b].z;
            o.w += c * xb[b].w;
        }
        *(float4*)(g_FW + ((size_t)r * N_NODES + n) * DOUT + d4) = o;
    }
}

// ---------------------------------------------------------------------------
// Scatter: out[row] += val * FW[col]  (one warp per edge, red.global.add.v4)
// ---------------------------------------------------------------------------
__global__ void scatter_kernel(const void* __restrict__ rows,
                               const void* __restrict__ cols,
                               const float* __restrict__ vals,
                               float* __restrict__ out) {
    const int lane = threadIdx.x & 31;
    const int e = (blockIdx.x * blockDim.x + threadIdx.x) >> 5;
    if (e >= NNZ) return;

    long long col, row;
    if (g_idx64) {
        col = ((const long long*)cols)[e];
        row = ((const long long*)rows)[e];
    } else {
        col = ((const int*)cols)[e];
        row = ((const int*)rows)[e];
    }
    const float v = vals[e];

    float4 d = *((const float4*)(g_FW + (size_t)col * DOUT) + lane);
    d.x *= v; d.y *= v; d.z *= v; d.w *= v;

    float* dst = out + (size_t)row * DOUT + lane * 4;
    asm volatile("red.global.add.v4.f32 [%0], {%1, %2, %3, %4};"
                 :: "l"(dst), "f"(d.x), "f"(d.y), "f"(d.z), "f"(d.w)
                 : "memory");
}

// ---------------------------------------------------------------------------
extern "C" void kernel_launch(void* const* d_in, const int* in_sizes, int n_in,
                              void* d_out, int out_size) {
    const float* X      = (const float*)d_in[0];
    const void*  A_rows = d_in[1];
    const void*  A_cols = d_in[2];
    const float* A_vals = (const float*)d_in[3];
    const float* basis  = (const float*)d_in[4];
    const float* comp   = (const float*)d_in[5];
    float* out = (float*)d_out;

    detect_dtype_kernel<<<1, 1>>>((const unsigned int*)A_rows);

    const int n4 = (N_NODES * DOUT) / 4;
    zero_out_kernel<<<(n4 + 255) / 256, 256>>>((float4*)out, n4);

    dim3 ggrid(M_TILES, B_BASES);
    gemm_xb_kernel<<<ggrid, 256>>>(X, basis);

    const int cthreads = N_NODES * 32;
    combine_kernel<<<(cthreads + 255) / 256, 256>>>(comp);

    const long long sthreads = (long long)NNZ * 32;
    scatter_kernel<<<(unsigned)((sthreads + 255) / 256), 256>>>(A_rows, A_cols, A_vals, out);
}

// round 4
// speedup vs baseline: 1.6192x; 1.1658x over previous
#include <cuda_runtime.h>
#include <cuda_bf16.h>
#include <cstdint>

#define N_NODES 50000
#define N_PAD   50048          // padded rows for bf16 X (multiple of 128)
#define R_REL   16
#define B_BASES 8
#define DIN     128
#define DOUT    128
#define NNZ     1600000
#define M_TILES 391            // ceil(50000/128)

typedef unsigned int uint;

// Scratch: device globals (no allocation allowed)
__device__ __nv_bfloat16 g_Xh[(size_t)N_PAD * DIN];            // 12.8 MB
__device__ __nv_bfloat16 g_Xl[(size_t)N_PAD * DIN];            // 12.8 MB
__device__ __nv_bfloat16 g_BTh[B_BASES * DOUT * DIN];          // 256 KB (BT[b][n][k])
__device__ __nv_bfloat16 g_BTl[B_BASES * DOUT * DIN];          // 256 KB
__device__ float g_XB[(size_t)B_BASES * N_NODES * DOUT];       // 204.8 MB
__device__ float g_FW[(size_t)R_REL * N_NODES * DOUT];         // 409.6 MB
__device__ int   g_idx64;

// ---------------------------------------------------------------------------
__device__ __forceinline__ uint32_t smem_u32(const void* p) {
    uint32_t a;
    asm("{ .reg .u64 t; cvta.to.shared.u64 t, %1; cvt.u32.u64 %0, t; }"
        : "=r"(a) : "l"(p));
    return a;
}
__device__ __forceinline__ void ldsm_x4(uint r[4], uint32_t addr) {
    asm volatile("ldmatrix.sync.aligned.m8n8.x4.shared.b16 {%0,%1,%2,%3}, [%4];"
                 : "=r"(r[0]), "=r"(r[1]), "=r"(r[2]), "=r"(r[3]) : "r"(addr));
}
__device__ __forceinline__ void mma_bf16(float c[4], const uint a[4], const uint b0, const uint b1) {
    asm volatile("mma.sync.aligned.m16n8k16.row.col.f32.bf16.bf16.f32 "
                 "{%0,%1,%2,%3},{%4,%5,%6,%7},{%8,%9},{%0,%1,%2,%3};"
                 : "+f"(c[0]), "+f"(c[1]), "+f"(c[2]), "+f"(c[3])
                 : "r"(a[0]), "r"(a[1]), "r"(a[2]), "r"(a[3]), "r"(b0), "r"(b1));
}

// ---------------------------------------------------------------------------
__global__ void detect_dtype_kernel(const unsigned int* __restrict__ rows_raw) {
    bool all_hi_zero = true;
    for (int i = 0; i < 64; i++)
        if (rows_raw[2 * i + 1] != 0u) { all_hi_zero = false; break; }
    g_idx64 = all_hi_zero ? 1 : 0;
}

__global__ void zero_out_kernel(float4* __restrict__ out, int n4) {
    int i = blockIdx.x * blockDim.x + threadIdx.x;
    if (i < n4) out[i] = make_float4(0.f, 0.f, 0.f, 0.f);
}

// Split X into bf16 hi/lo. Each thread handles 8 consecutive elements.
__global__ void prep_x_kernel(const float* __restrict__ X) {
    const int id = blockIdx.x * blockDim.x + threadIdx.x;
    if (id >= (N_PAD * DIN) / 8) return;
    const size_t base = (size_t)id * 8;
    const int row = (int)(base >> 7);
    __nv_bfloat16 h[8], l[8];
    if (row < N_NODES) {
        float v[8];
        *(float4*)&v[0] = *(const float4*)(X + base);
        *(float4*)&v[4] = *(const float4*)(X + base + 4);
#pragma unroll
        for (int i = 0; i < 8; i++) {
            h[i] = __float2bfloat16_rn(v[i]);
            l[i] = __float2bfloat16_rn(v[i] - __bfloat162float(h[i]));
        }
    } else {
#pragma unroll
        for (int i = 0; i < 8; i++) { h[i] = __float2bfloat16_rn(0.f); l[i] = h[i]; }
    }
    *(uint4*)(g_Xh + base) = *(uint4*)h;
    *(uint4*)(g_Xl + base) = *(uint4*)l;
}

// Transpose + split basis: BT[b][n][k] = basis[b][k][n]
__global__ void prep_bt_kernel(const float* __restrict__ basis) {
    const int id = blockIdx.x * blockDim.x + threadIdx.x;   // (b, n, k4)
    if (id >= B_BASES * DOUT * (DIN / 4)) return;
    const int k4 = (id & 31) * 4;
    const int n  = (id >> 5) & 127;
    const int b  = id >> 12;
    __nv_bfloat16 h[4], l[4];
#pragma unroll
    for (int i = 0; i < 4; i++) {
        float v = basis[(size_t)b * DIN * DOUT + (size_t)(k4 + i) * DOUT + n];
        h[i] = __float2bfloat16_rn(v);
        l[i] = __float2bfloat16_rn(v - __bfloat162float(h[i]));
    }
    const size_t off = (size_t)b * DOUT * DIN + (size_t)n * DIN + k4;
    *(uint2*)(g_BTh + off) = *(uint2*)h;
    *(uint2*)(g_BTl + off) = *(uint2*)l;
}

// ---------------------------------------------------------------------------
// XB[b] = X @ basis[b] via mma.sync bf16 split-3.
// grid (M_TILES, B_BASES), 256 threads (8 warps, warp grid 4m x 2n).
// Smem: full 128x128 K-panel of Xh/Xl tile and BTh/BTl (rows padded to 136 bf16).
// ---------------------------------------------------------------------------
#define SROW 136                       // padded row stride in bf16 (272 B)
#define S_XH 0
#define S_XL (128 * SROW * 2)          // 34816
#define S_BH (2 * 128 * SROW * 2)      // 69632
#define S_BL (3 * 128 * SROW * 2)      // 104448
#define S_TOTAL (4 * 128 * SROW * 2)   // 139264

__global__ void __launch_bounds__(256, 1)
gemm_mma_kernel(int dummy) {
    extern __shared__ __align__(256) unsigned char smem[];
    const uint32_t sbase = smem_u32(smem);
    const int tid  = threadIdx.x;
    const int wid  = tid >> 5;
    const int lane = tid & 31;
    const int b    = blockIdx.y;
    const int m0   = blockIdx.x * 128;

    // --- load tiles: each thread copies half a row (128 B) per array ---
    {
        const int row  = tid >> 1;
        const int half = (tid & 1) * 64;              // bf16 offset
        const uint4* srcXh = (const uint4*)(g_Xh + (size_t)(m0 + row) * DIN + half);
        const uint4* srcXl = (const uint4*)(g_Xl + (size_t)(m0 + row) * DIN + half);
        const uint4* srcBh = (const uint4*)(g_BTh + (size_t)b * DOUT * DIN + (size_t)row * DIN + half);
        const uint4* srcBl = (const uint4*)(g_BTl + (size_t)b * DOUT * DIN + (size_t)row * DIN + half);
        uint4* dXh = (uint4*)(smem + S_XH + row * SROW * 2 + half * 2);
        uint4* dXl = (uint4*)(smem + S_XL + row * SROW * 2 + half * 2);
        uint4* dBh = (uint4*)(smem + S_BH + row * SROW * 2 + half * 2);
        uint4* dBl = (uint4*)(smem + S_BL + row * SROW * 2 + half * 2);
#pragma unroll
        for (int i = 0; i < 8; i++) {
            dXh[i] = srcXh[i];
            dXl[i] = srcXl[i];
            dBh[i] = srcBh[i];
            dBl[i] = srcBl[i];
        }
    }
    __syncthreads();

    const int wm = wid >> 1;          // 0..3  (32 rows)
    const int wn = wid & 1;           // 0..1  (64 cols)

    float acc[2][8][4];
#pragma unroll
    for (int mf = 0; mf < 2; mf++)
#pragma unroll
        for (int nf = 0; nf < 8; nf++)
#pragma unroll
            for (int q = 0; q < 4; q++) acc[mf][nf][q] = 0.f;

    // ldmatrix lane-address components
    const int a_row = wm * 32 + (lane & 15);                 // + mf*16
    const int a_colb = ((lane >> 4) * 8) * 2;                // byte offset within k16
    const int b_row = wn * 64 + (lane & 7) + ((lane >> 4) << 3);  // + p*16
    const int b_colb = (((lane >> 3) & 1) * 8) * 2;

#pragma unroll
    for (int kf = 0; kf < 8; kf++) {
        const int kb = kf * 16 * 2;   // k byte base
        uint Ah[2][4], Al[2][4];
#pragma unroll
        for (int mf = 0; mf < 2; mf++) {
            const uint32_t arow = (uint32_t)(a_row + mf * 16) * (SROW * 2) + kb + a_colb;
            ldsm_x4(Ah[mf], sbase + S_XH + arow);
            ldsm_x4(Al[mf], sbase + S_XL + arow);
        }
        uint Bh[4][4], Bl[4][4];
#pragma unroll
        for (int p = 0; p < 4; p++) {
            const uint32_t brow = (uint32_t)(b_row + p * 16) * (SROW * 2) + kb + b_colb;
            ldsm_x4(Bh[p], sbase + S_BH + brow);
            ldsm_x4(Bl[p], sbase + S_BL + brow);
        }
#pragma unroll
        for (int mf = 0; mf < 2; mf++)
#pragma unroll
            for (int p = 0; p < 4; p++) {
                // oct 2p: regs {0,1}; oct 2p+1: regs {2,3}
                mma_bf16(acc[mf][2 * p],     Ah[mf], Bh[p][0], Bh[p][1]);
                mma_bf16(acc[mf][2 * p],     Ah[mf], Bl[p][0], Bl[p][1]);
                mma_bf16(acc[mf][2 * p],     Al[mf], Bh[p][0], Bh[p][1]);
                mma_bf16(acc[mf][2 * p + 1], Ah[mf], Bh[p][2], Bh[p][3]);
                mma_bf16(acc[mf][2 * p + 1], Ah[mf], Bl[p][2], Bl[p][3]);
                mma_bf16(acc[mf][2 * p + 1], Al[mf], Bh[p][2], Bh[p][3]);
            }
    }

    // --- epilogue: write XB[b] fp32 ---
    float* outBase = g_XB + (size_t)b * N_NODES * DOUT;
    const int g = lane >> 2;
    const int t2 = (lane & 3) * 2;
#pragma unroll
    for (int mf = 0; mf < 2; mf++) {
        const int r0 = m0 + wm * 32 + mf * 16 + g;
#pragma unroll
        for (int nf = 0; nf < 8; nf++) {
            const int col = wn * 64 + nf * 8 + t2;
            if (r0 < N_NODES)
                *(float2*)(outBase + (size_t)r0 * DOUT + col) =
                    make_float2(acc[mf][nf][0], acc[mf][nf][1]);
            if (r0 + 8 < N_NODES)
                *(float2*)(outBase + (size_t)(r0 + 8) * DOUT + col) =
                    make_float2(acc[mf][nf][2], acc[mf][nf][3]);
        }
    }
}

// ---------------------------------------------------------------------------
// FW[r][n][d] = sum_b comp[r][b] * XB[b][n][d]   (memory-bound, ~78% HBM)
// ---------------------------------------------------------------------------
__global__ __launch_bounds__(256)
void combine_kernel(const float* __restrict__ comp) {
    __shared__ float cs[R_REL * B_BASES];
    if (threadIdx.x < R_REL * B_BASES) cs[threadIdx.x] = comp[threadIdx.x];
    __syncthreads();

    const int id = blockIdx.x * blockDim.x + threadIdx.x;
    if (id >= N_NODES * 32) return;
    const int n  = id >> 5;
    const int d4 = (id & 31) * 4;

    float4 xb[8];
#pragma unroll
    for (int b = 0; b < B_BASES; b++)
        xb[b] = __ldg((const float4*)(g_XB + ((size_t)b * N_NODES + n) * DOUT + d4));

#pragma unroll
    for (int r = 0; r < R_REL; r++) {
        float4 o = make_float4(0.f, 0.f, 0.f, 0.f);
#pragma unroll
        for (int b = 0; b < B_BASES; b++) {
            const float c = cs[r * B_BASES + b];
            o.x += c * xb[b].x;
            o.y += c * xb[b].y;
            o.z += c * xb[b].z;
            o.w += c * xb[b].w;
        }
        *(float4*)(g_FW + ((size_t)r * N_NODES + n) * DOUT + d4) = o;
    }
}

// ---------------------------------------------------------------------------
// Scatter: out[row] += val * FW[col]  (one warp per edge, red.global.add.v4)
// ---------------------------------------------------------------------------
__global__ void scatter_kernel(const void* __restrict__ rows,
                               const void* __restrict__ cols,
                               const float* __restrict__ vals,
                               float* __restrict__ out) {
    const int lane = threadIdx.x & 31;
    const int e = (blockIdx.x * blockDim.x + threadIdx.x) >> 5;
    if (e >= NNZ) return;

    long long col, row;
    if (g_idx64) {
        col = ((const long long*)cols)[e];
        row = ((const long long*)rows)[e];
    } else {
        col = ((const int*)cols)[e];
        row = ((const int*)rows)[e];
    }
    const float v = vals[e];

    float4 d = __ldg((const float4*)(g_FW + (size_t)col * DOUT) + lane);
    d.x *= v; d.y *= v; d.z *= v; d.w *= v;

    float* dst = out + (size_t)row * DOUT + lane * 4;
    asm volatile("red.global.add.v4.f32 [%0], {%1, %2, %3, %4};"
                 :: "l"(dst), "f"(d.x), "f"(d.y), "f"(d.z), "f"(d.w)
                 : "memory");
}

// ---------------------------------------------------------------------------
extern "C" void kernel_launch(void* const* d_in, const int* in_sizes, int n_in,
                              void* d_out, int out_size) {
    const float* X      = (const float*)d_in[0];
    const void*  A_rows = d_in[1];
    const void*  A_cols = d_in[2];
    const float* A_vals = (const float*)d_in[3];
    const float* basis  = (const float*)d_in[4];
    const float* comp   = (const float*)d_in[5];
    float* out = (float*)d_out;

    cudaFuncSetAttribute(gemm_mma_kernel,
                         cudaFuncAttributeMaxDynamicSharedMemorySize, S_TOTAL);

    detect_dtype_kernel<<<1, 1>>>((const unsigned int*)A_rows);

    const int n4 = (N_NODES * DOUT) / 4;
    zero_out_kernel<<<(n4 + 255) / 256, 256>>>((float4*)out, n4);

    const int px = (N_PAD * DIN) / 8;
    prep_x_kernel<<<(px + 255) / 256, 256>>>(X);
    const int pb = B_BASES * DOUT * (DIN / 4);
    prep_bt_kernel<<<(pb + 255) / 256, 256>>>(basis);

    dim3 ggrid(M_TILES, B_BASES);
    gemm_mma_kernel<<<ggrid, 256, S_TOTAL>>>(0);

    const int cthreads = N_NODES * 32;
    combine_kernel<<<(cthreads + 255) / 256, 256>>>(comp);

    const long long sthreads = (long long)NNZ * 32;
    scatter_kernel<<<(unsigned)((sthreads + 255) / 256), 256>>>(A_rows, A_cols, A_vals, out);
}

// round 5
// speedup vs baseline: 1.7551x; 1.0839x over previous
#include <cuda_runtime.h>
#include <cuda_bf16.h>
#include <cstdint>

#define N_NODES 50000
#define N_PAD   50048
#define R_REL   16
#define B_BASES 8
#define DIN     128
#define DOUT    128
#define NNZ     1600000
#define M_TILES 391

typedef unsigned int uint;

// Scratch: device globals (no allocation allowed)
__device__ __nv_bfloat16 g_Xh[(size_t)N_PAD * DIN];
__device__ __nv_bfloat16 g_Xl[(size_t)N_PAD * DIN];
__device__ __nv_bfloat16 g_BTh[B_BASES * DOUT * DIN];
__device__ __nv_bfloat16 g_BTl[B_BASES * DOUT * DIN];
__device__ float g_XB[(size_t)B_BASES * N_NODES * DOUT];   // 204.8 MB
__device__ float g_FW[(size_t)R_REL * N_NODES * DOUT];     // 409.6 MB
__device__ int   g_idx64;
// CSR binning scratch
__device__ int   g_cnt[N_NODES];
__device__ int   g_start[N_NODES + 1];
__device__ int   g_cursor[N_NODES];
__device__ int2  g_edge[NNZ];                              // (col, val bits) 12.8 MB

// ---------------------------------------------------------------------------
__device__ __forceinline__ uint32_t smem_u32(const void* p) {
    uint32_t a;
    asm("{ .reg .u64 t; cvta.to.shared.u64 t, %1; cvt.u32.u64 %0, t; }"
        : "=r"(a) : "l"(p));
    return a;
}
__device__ __forceinline__ void ldsm_x4(uint r[4], uint32_t addr) {
    asm volatile("ldmatrix.sync.aligned.m8n8.x4.shared.b16 {%0,%1,%2,%3}, [%4];"
                 : "=r"(r[0]), "=r"(r[1]), "=r"(r[2]), "=r"(r[3]) : "r"(addr));
}
__device__ __forceinline__ void mma_bf16(float c[4], const uint a[4], const uint b0, const uint b1) {
    asm volatile("mma.sync.aligned.m16n8k16.row.col.f32.bf16.bf16.f32 "
                 "{%0,%1,%2,%3},{%4,%5,%6,%7},{%8,%9},{%0,%1,%2,%3};"
                 : "+f"(c[0]), "+f"(c[1]), "+f"(c[2]), "+f"(c[3])
                 : "r"(a[0]), "r"(a[1]), "r"(a[2]), "r"(a[3]), "r"(b0), "r"(b1));
}

// ---------------------------------------------------------------------------
__global__ void detect_dtype_kernel(const unsigned int* __restrict__ rows_raw) {
    bool all_hi_zero = true;
    for (int i = 0; i < 64; i++)
        if (rows_raw[2 * i + 1] != 0u) { all_hi_zero = false; break; }
    g_idx64 = all_hi_zero ? 1 : 0;
}

__global__ void zero_cnt_kernel() {
    int i = blockIdx.x * blockDim.x + threadIdx.x;
    if (i < N_NODES) g_cnt[i] = 0;
}

// Histogram of output rows
__global__ void hist_kernel(const void* __restrict__ rows) {
    const int e = blockIdx.x * blockDim.x + threadIdx.x;
    if (e >= NNZ) return;
    int row = g_idx64 ? (int)((const unsigned int*)rows)[2 * e]
                      : ((const int*)rows)[e];
    atomicAdd(&g_cnt[row], 1);
}

// Single-block exclusive scan of g_cnt -> g_start / g_cursor
__global__ void __launch_bounds__(1024, 1) scan_kernel() {
    __shared__ int wsum[32];
    __shared__ int carry;
    const int tid = threadIdx.x, lane = tid & 31, wid = tid >> 5;
    if (tid == 0) carry = 0;
    __syncthreads();
    for (int base = 0; base < N_NODES; base += 1024) {
        const int i = base + tid;
        int v = (i < N_NODES) ? g_cnt[i] : 0;
        int x = v;
#pragma unroll
        for (int off = 1; off < 32; off <<= 1) {
            int y = __shfl_up_sync(0xffffffffu, x, off);
            if (lane >= off) x += y;
        }
        if (lane == 31) wsum[wid] = x;
        __syncthreads();
        if (wid == 0) {
            int s = wsum[lane];
#pragma unroll
            for (int off = 1; off < 32; off <<= 1) {
                int y = __shfl_up_sync(0xffffffffu, s, off);
                if (lane >= off) s += y;
            }
            wsum[lane] = s;
        }
        __syncthreads();
        const int warpOff = (wid == 0) ? 0 : wsum[wid - 1];
        const int excl = carry + warpOff + x - v;
        if (i < N_NODES) { g_start[i] = excl; g_cursor[i] = excl; }
        __syncthreads();
        if (tid == 0) carry += wsum[31];
        __syncthreads();
    }
    if (tid == 0) g_start[N_NODES] = carry;
}

// Fill CSR buckets with packed (col, val)
__global__ void fill_kernel(const void* __restrict__ rows,
                            const void* __restrict__ cols,
                            const float* __restrict__ vals) {
    const int e = blockIdx.x * blockDim.x + threadIdx.x;
    if (e >= NNZ) return;
    int row, col;
    if (g_idx64) {
        row = (int)((const unsigned int*)rows)[2 * e];
        col = (int)((const unsigned int*)cols)[2 * e];
    } else {
        row = ((const int*)rows)[e];
        col = ((const int*)cols)[e];
    }
    const int pos = atomicAdd(&g_cursor[row], 1);
    g_edge[pos] = make_int2(col, __float_as_int(vals[e]));
}

// ---------------------------------------------------------------------------
__global__ void prep_x_kernel(const float* __restrict__ X) {
    const int id = blockIdx.x * blockDim.x + threadIdx.x;
    if (id >= (N_PAD * DIN) / 8) return;
    const size_t base = (size_t)id * 8;
    const int row = (int)(base >> 7);
    __nv_bfloat16 h[8], l[8];
    if (row < N_NODES) {
        float v[8];
        *(float4*)&v[0] = *(const float4*)(X + base);
        *(float4*)&v[4] = *(const float4*)(X + base + 4);
#pragma unroll
        for (int i = 0; i < 8; i++) {
            h[i] = __float2bfloat16_rn(v[i]);
            l[i] = __float2bfloat16_rn(v[i] - __bfloat162float(h[i]));
        }
    } else {
#pragma unroll
        for (int i = 0; i < 8; i++) { h[i] = __float2bfloat16_rn(0.f); l[i] = h[i]; }
    }
    *(uint4*)(g_Xh + base) = *(uint4*)h;
    *(uint4*)(g_Xl + base) = *(uint4*)l;
}

__global__ void prep_bt_kernel(const float* __restrict__ basis) {
    const int id = blockIdx.x * blockDim.x + threadIdx.x;
    if (id >= B_BASES * DOUT * (DIN / 4)) return;
    const int k4 = (id & 31) * 4;
    const int n  = (id >> 5) & 127;
    const int b  = id >> 12;
    __nv_bfloat16 h[4], l[4];
#pragma unroll
    for (int i = 0; i < 4; i++) {
        float v = basis[(size_t)b * DIN * DOUT + (size_t)(k4 + i) * DOUT + n];
        h[i] = __float2bfloat16_rn(v);
        l[i] = __float2bfloat16_rn(v - __bfloat162float(h[i]));
    }
    const size_t off = (size_t)b * DOUT * DIN + (size_t)n * DIN + k4;
    *(uint2*)(g_BTh + off) = *(uint2*)h;
    *(uint2*)(g_BTl + off) = *(uint2*)l;
}

// ---------------------------------------------------------------------------
// XB[b] = X @ basis[b] via mma.sync bf16 split-3 (unchanged from R4)
// ---------------------------------------------------------------------------
#define SROW 136
#define S_XH 0
#define S_XL (128 * SROW * 2)
#define S_BH (2 * 128 * SROW * 2)
#define S_BL (3 * 128 * SROW * 2)
#define S_TOTAL (4 * 128 * SROW * 2)

__global__ void __launch_bounds__(256, 1)
gemm_mma_kernel(int dummy) {
    extern __shared__ __align__(256) unsigned char smem[];
    const uint32_t sbase = smem_u32(smem);
    const int tid  = threadIdx.x;
    const int wid  = tid >> 5;
    const int lane = tid & 31;
    const int b    = blockIdx.y;
    const int m0   = blockIdx.x * 128;

    {
        const int row  = tid >> 1;
        const int half = (tid & 1) * 64;
        const uint4* srcXh = (const uint4*)(g_Xh + (size_t)(m0 + row) * DIN + half);
        const uint4* srcXl = (const uint4*)(g_Xl + (size_t)(m0 + row) * DIN + half);
        const uint4* srcBh = (const uint4*)(g_BTh + (size_t)b * DOUT * DIN + (size_t)row * DIN + half);
        const uint4* srcBl = (const uint4*)(g_BTl + (size_t)b * DOUT * DIN + (size_t)row * DIN + half);
        uint4* dXh = (uint4*)(smem + S_XH + row * SROW * 2 + half * 2);
        uint4* dXl = (uint4*)(smem + S_XL + row * SROW * 2 + half * 2);
        uint4* dBh = (uint4*)(smem + S_BH + row * SROW * 2 + half * 2);
        uint4* dBl = (uint4*)(smem + S_BL + row * SROW * 2 + half * 2);
#pragma unroll
        for (int i = 0; i < 8; i++) {
            dXh[i] = srcXh[i];
            dXl[i] = srcXl[i];
            dBh[i] = srcBh[i];
            dBl[i] = srcBl[i];
        }
    }
    __syncthreads();

    const int wm = wid >> 1;
    const int wn = wid & 1;

    float acc[2][8][4];
#pragma unroll
    for (int mf = 0; mf < 2; mf++)
#pragma unroll
        for (int nf = 0; nf < 8; nf++)
#pragma unroll
            for (int q = 0; q < 4; q++) acc[mf][nf][q] = 0.f;

    const int a_row  = wm * 32 + (lane & 15);
    const int a_colb = ((lane >> 4) * 8) * 2;
    const int b_row  = wn * 64 + (lane & 7) + ((lane >> 4) << 3);
    const int b_colb = (((lane >> 3) & 1) * 8) * 2;

#pragma unroll
    for (int kf = 0; kf < 8; kf++) {
        const int kb = kf * 16 * 2;
        uint Ah[2][4], Al[2][4];
#pragma unroll
        for (int mf = 0; mf < 2; mf++) {
            const uint32_t arow = (uint32_t)(a_row + mf * 16) * (SROW * 2) + kb + a_colb;
            ldsm_x4(Ah[mf], sbase + S_XH + arow);
            ldsm_x4(Al[mf], sbase + S_XL + arow);
        }
        uint Bh[4][4], Bl[4][4];
#pragma unroll
        for (int p = 0; p < 4; p++) {
            const uint32_t brow = (uint32_t)(b_row + p * 16) * (SROW * 2) + kb + b_colb;
            ldsm_x4(Bh[p], sbase + S_BH + brow);
            ldsm_x4(Bl[p], sbase + S_BL + brow);
        }
#pragma unroll
        for (int mf = 0; mf < 2; mf++)
#pragma unroll
            for (int p = 0; p < 4; p++) {
                mma_bf16(acc[mf][2 * p],     Ah[mf], Bh[p][0], Bh[p][1]);
                mma_bf16(acc[mf][2 * p],     Ah[mf], Bl[p][0], Bl[p][1]);
                mma_bf16(acc[mf][2 * p],     Al[mf], Bh[p][0], Bh[p][1]);
                mma_bf16(acc[mf][2 * p + 1], Ah[mf], Bh[p][2], Bh[p][3]);
                mma_bf16(acc[mf][2 * p + 1], Ah[mf], Bl[p][2], Bl[p][3]);
                mma_bf16(acc[mf][2 * p + 1], Al[mf], Bh[p][2], Bh[p][3]);
            }
    }

    float* outBase = g_XB + (size_t)b * N_NODES * DOUT;
    const int g = lane >> 2;
    const int t2 = (lane & 3) * 2;
#pragma unroll
    for (int mf = 0; mf < 2; mf++) {
        const int r0 = m0 + wm * 32 + mf * 16 + g;
#pragma unroll
        for (int nf = 0; nf < 8; nf++) {
            const int col = wn * 64 + nf * 8 + t2;
            if (r0 < N_NODES)
                *(float2*)(outBase + (size_t)r0 * DOUT + col) =
                    make_float2(acc[mf][nf][0], acc[mf][nf][1]);
            if (r0 + 8 < N_NODES)
                *(float2*)(outBase + (size_t)(r0 + 8) * DOUT + col) =
                    make_float2(acc[mf][nf][2], acc[mf][nf][3]);
        }
    }
}

// ---------------------------------------------------------------------------
// FW[r][n][d] = sum_b comp[r][b] * XB[b][n][d]
// ---------------------------------------------------------------------------
__global__ __launch_bounds__(256)
void combine_kernel(const float* __restrict__ comp) {
    __shared__ float cs[R_REL * B_BASES];
    if (threadIdx.x < R_REL * B_BASES) cs[threadIdx.x] = comp[threadIdx.x];
    __syncthreads();

    const int id = blockIdx.x * blockDim.x + threadIdx.x;
    if (id >= N_NODES * 32) return;
    const int n  = id >> 5;
    const int d4 = (id & 31) * 4;

    float4 xb[8];
#pragma unroll
    for (int b = 0; b < B_BASES; b++)
        xb[b] = __ldg((const float4*)(g_XB + ((size_t)b * N_NODES + n) * DOUT + d4));

#pragma unroll
    for (int r = 0; r < R_REL; r++) {
        float4 o = make_float4(0.f, 0.f, 0.f, 0.f);
#pragma unroll
        for (int b = 0; b < B_BASES; b++) {
            const float c = cs[r * B_BASES + b];
            o.x += c * xb[b].x;
            o.y += c * xb[b].y;
            o.z += c * xb[b].z;
            o.w += c * xb[b].w;
        }
        *(float4*)(g_FW + ((size_t)r * N_NODES + n) * DOUT + d4) = o;
    }
}

// ---------------------------------------------------------------------------
// Sorted scatter: one warp per output row; register accumulation; single
// non-atomic row write. Covers every row, so no separate zeroing of out.
// ---------------------------------------------------------------------------
__global__ void __launch_bounds__(256)
scatter2_kernel(float* __restrict__ out) {
    const int warpId = (blockIdx.x * blockDim.x + threadIdx.x) >> 5;
    if (warpId >= N_NODES) return;
    const int lane = threadIdx.x & 31;

    const int s = g_start[warpId];
    const int e = g_start[warpId + 1];

    float4 acc = make_float4(0.f, 0.f, 0.f, 0.f);
    int i = s;
    for (; i + 4 <= e; i += 4) {
        int2 e0 = g_edge[i], e1 = g_edge[i + 1], e2 = g_edge[i + 2], e3 = g_edge[i + 3];
        float4 f0 = __ldg((const float4*)(g_FW + (size_t)e0.x * DOUT) + lane);
        float4 f1 = __ldg((const float4*)(g_FW + (size_t)e1.x * DOUT) + lane);
        float4 f2 = __ldg((const float4*)(g_FW + (size_t)e2.x * DOUT) + lane);
        float4 f3 = __ldg((const float4*)(g_FW + (size_t)e3.x * DOUT) + lane);
        const float v0 = __int_as_float(e0.y), v1 = __int_as_float(e1.y);
        const float v2 = __int_as_float(e2.y), v3 = __int_as_float(e3.y);
        acc.x += v0 * f0.x + v1 * f1.x + v2 * f2.x + v3 * f3.x;
        acc.y += v0 * f0.y + v1 * f1.y + v2 * f2.y + v3 * f3.y;
        acc.z += v0 * f0.z + v1 * f1.z + v2 * f2.z + v3 * f3.z;
        acc.w += v0 * f0.w + v1 * f1.w + v2 * f2.w + v3 * f3.w;
    }
    for (; i < e; i++) {
        int2 ed = g_edge[i];
        float4 f = __ldg((const float4*)(g_FW + (size_t)ed.x * DOUT) + lane);
        const float v = __int_as_float(ed.y);
        acc.x += v * f.x; acc.y += v * f.y; acc.z += v * f.z; acc.w += v * f.w;
    }
    *(float4*)(out + (size_t)warpId * DOUT + lane * 4) = acc;
}

// ---------------------------------------------------------------------------
extern "C" void kernel_launch(void* const* d_in, const int* in_sizes, int n_in,
                              void* d_out, int out_size) {
    const float* X      = (const float*)d_in[0];
    const void*  A_rows = d_in[1];
    const void*  A_cols = d_in[2];
    const float* A_vals = (const float*)d_in[3];
    const float* basis  = (const float*)d_in[4];
    const float* comp   = (const float*)d_in[5];
    float* out = (float*)d_out;

    cudaFuncSetAttribute(gemm_mma_kernel,
                         cudaFuncAttributeMaxDynamicSharedMemorySize, S_TOTAL);

    detect_dtype_kernel<<<1, 1>>>((const unsigned int*)A_rows);
    zero_cnt_kernel<<<(N_NODES + 255) / 256, 256>>>();

    const int px = (N_PAD * DIN) / 8;
    prep_x_kernel<<<(px + 255) / 256, 256>>>(X);
    const int pb = B_BASES * DOUT * (DIN / 4);
    prep_bt_kernel<<<(pb + 255) / 256, 256>>>(basis);

    hist_kernel<<<(NNZ + 255) / 256, 256>>>(A_rows);
    scan_kernel<<<1, 1024>>>();
    fill_kernel<<<(NNZ + 255) / 256, 256>>>(A_rows, A_cols, A_vals);

    dim3 ggrid(M_TILES, B_BASES);
    gemm_mma_kernel<<<ggrid, 256, S_TOTAL>>>(0);

    const int cthreads = N_NODES * 32;
    combine_kernel<<<(cthreads + 255) / 256, 256>>>(comp);

    const long long sthreads = (long long)N_NODES * 32;
    scatter2_kernel<<<(unsigned)((sthreads + 255) / 256), 256>>>(out);
}

// round 6
// speedup vs baseline: 1.9909x; 1.1344x over previous
#include <cuda_runtime.h>
#include <cuda_bf16.h>
#include <cstdint>

#define N_NODES 50000
#define N_PAD   50048
#define R_REL   16
#define B_BASES 8
#define DIN     128
#define DOUT    128
#define NNZ     1600000
#define M_TILES 391

typedef unsigned int uint;

// Scratch: device globals (no allocation allowed)
__device__ __nv_bfloat16 g_Xh[(size_t)N_PAD * DIN];
__device__ __nv_bfloat16 g_Xl[(size_t)N_PAD * DIN];
__device__ __nv_bfloat16 g_BTh[B_BASES * DOUT * DIN];
__device__ __nv_bfloat16 g_BTl[B_BASES * DOUT * DIN];
__device__ float g_XB[(size_t)B_BASES * N_NODES * DOUT];   // 204.8 MB
__device__ float g_FW[(size_t)R_REL * N_NODES * DOUT];     // 409.6 MB
__device__ int   g_idx64;
// CSR binning scratch
__device__ int   g_cnt[N_NODES];
__device__ int   g_start[N_NODES + 1];
__device__ int   g_cursor[N_NODES];
__device__ int2  g_edge[NNZ];

// ---------------------------------------------------------------------------
__device__ __forceinline__ uint32_t smem_u32(const void* p) {
    uint32_t a;
    asm("{ .reg .u64 t; cvta.to.shared.u64 t, %1; cvt.u32.u64 %0, t; }"
        : "=r"(a) : "l"(p));
    return a;
}
__device__ __forceinline__ void ldsm_x4(uint r[4], uint32_t addr) {
    asm volatile("ldmatrix.sync.aligned.m8n8.x4.shared.b16 {%0,%1,%2,%3}, [%4];"
                 : "=r"(r[0]), "=r"(r[1]), "=r"(r[2]), "=r"(r[3]) : "r"(addr));
}
__device__ __forceinline__ void mma_bf16(float c[4], const uint a[4], const uint b0, const uint b1) {
    asm volatile("mma.sync.aligned.m16n8k16.row.col.f32.bf16.bf16.f32 "
                 "{%0,%1,%2,%3},{%4,%5,%6,%7},{%8,%9},{%0,%1,%2,%3};"
                 : "+f"(c[0]), "+f"(c[1]), "+f"(c[2]), "+f"(c[3])
                 : "r"(a[0]), "r"(a[1]), "r"(a[2]), "r"(a[3]), "r"(b0), "r"(b1));
}

// ---------------------------------------------------------------------------
__global__ void detect_dtype_kernel(const unsigned int* __restrict__ rows_raw) {
    bool all_hi_zero = true;
    for (int i = 0; i < 64; i++)
        if (rows_raw[2 * i + 1] != 0u) { all_hi_zero = false; break; }
    g_idx64 = all_hi_zero ? 1 : 0;
}

__global__ void zero_cnt_kernel() {
    int i = blockIdx.x * blockDim.x + threadIdx.x;
    if (i < N_NODES) g_cnt[i] = 0;
}

__global__ void hist_kernel(const void* __restrict__ rows) {
    const int e = blockIdx.x * blockDim.x + threadIdx.x;
    if (e >= NNZ) return;
    int row = g_idx64 ? (int)((const unsigned int*)rows)[2 * e]
                      : ((const int*)rows)[e];
    atomicAdd(&g_cnt[row], 1);
}

__global__ void __launch_bounds__(1024, 1) scan_kernel() {
    __shared__ int wsum[32];
    __shared__ int carry;
    const int tid = threadIdx.x, lane = tid & 31, wid = tid >> 5;
    if (tid == 0) carry = 0;
    __syncthreads();
    for (int base = 0; base < N_NODES; base += 1024) {
        const int i = base + tid;
        int v = (i < N_NODES) ? g_cnt[i] : 0;
        int x = v;
#pragma unroll
        for (int off = 1; off < 32; off <<= 1) {
            int y = __shfl_up_sync(0xffffffffu, x, off);
            if (lane >= off) x += y;
        }
        if (lane == 31) wsum[wid] = x;
        __syncthreads();
        if (wid == 0) {
            int s = wsum[lane];
#pragma unroll
            for (int off = 1; off < 32; off <<= 1) {
                int y = __shfl_up_sync(0xffffffffu, s, off);
                if (lane >= off) s += y;
            }
            wsum[lane] = s;
        }
        __syncthreads();
        const int warpOff = (wid == 0) ? 0 : wsum[wid - 1];
        const int excl = carry + warpOff + x - v;
        if (i < N_NODES) { g_start[i] = excl; g_cursor[i] = excl; }
        __syncthreads();
        if (tid == 0) carry += wsum[31];
        __syncthreads();
    }
    if (tid == 0) g_start[N_NODES] = carry;
}

__global__ void fill_kernel(const void* __restrict__ rows,
                            const void* __restrict__ cols,
                            const float* __restrict__ vals) {
    const int e = blockIdx.x * blockDim.x + threadIdx.x;
    if (e >= NNZ) return;
    int row, col;
    if (g_idx64) {
        row = (int)((const unsigned int*)rows)[2 * e];
        col = (int)((const unsigned int*)cols)[2 * e];
    } else {
        row = ((const int*)rows)[e];
        col = ((const int*)cols)[e];
    }
    const int pos = atomicAdd(&g_cursor[row], 1);
    g_edge[pos] = make_int2(col, __float_as_int(vals[e]));
}

// ---------------------------------------------------------------------------
__global__ void prep_x_kernel(const float* __restrict__ X) {
    const int id = blockIdx.x * blockDim.x + threadIdx.x;
    if (id >= (N_PAD * DIN) / 8) return;
    const size_t base = (size_t)id * 8;
    const int row = (int)(base >> 7);
    __nv_bfloat16 h[8], l[8];
    if (row < N_NODES) {
        float v[8];
        *(float4*)&v[0] = *(const float4*)(X + base);
        *(float4*)&v[4] = *(const float4*)(X + base + 4);
#pragma unroll
        for (int i = 0; i < 8; i++) {
            h[i] = __float2bfloat16_rn(v[i]);
            l[i] = __float2bfloat16_rn(v[i] - __bfloat162float(h[i]));
        }
    } else {
#pragma unroll
        for (int i = 0; i < 8; i++) { h[i] = __float2bfloat16_rn(0.f); l[i] = h[i]; }
    }
    *(uint4*)(g_Xh + base) = *(uint4*)h;
    *(uint4*)(g_Xl + base) = *(uint4*)l;
}

__global__ void prep_bt_kernel(const float* __restrict__ basis) {
    const int id = blockIdx.x * blockDim.x + threadIdx.x;
    if (id >= B_BASES * DOUT * (DIN / 4)) return;
    const int k4 = (id & 31) * 4;
    const int n  = (id >> 5) & 127;
    const int b  = id >> 12;
    __nv_bfloat16 h[4], l[4];
#pragma unroll
    for (int i = 0; i < 4; i++) {
        float v = basis[(size_t)b * DIN * DOUT + (size_t)(k4 + i) * DOUT + n];
        h[i] = __float2bfloat16_rn(v);
        l[i] = __float2bfloat16_rn(v - __bfloat162float(h[i]));
    }
    const size_t off = (size_t)b * DOUT * DIN + (size_t)n * DIN + k4;
    *(uint2*)(g_BTh + off) = *(uint2*)h;
    *(uint2*)(g_BTl + off) = *(uint2*)l;
}

// ---------------------------------------------------------------------------
// XB[b] = X @ basis[b] via mma.sync bf16 split-3.
// K-chunked (2 x 64) + XOR swizzle: 64 KB smem/CTA -> 2 CTAs/SM.
// Row stride 128 B (64 bf16); 16B chunk index swizzled with (row & 7).
// ---------------------------------------------------------------------------
#define S_XH 0
#define S_XL 16384
#define S_BH 32768
#define S_BL 49152
#define S_TOTAL 65536

__global__ void __launch_bounds__(256, 2)
gemm_mma_kernel(int dummy) {
    extern __shared__ __align__(1024) unsigned char smem[];
    const uint32_t sbase = smem_u32(smem);
    const int tid  = threadIdx.x;
    const int wid  = tid >> 5;
    const int lane = tid & 31;
    const int b    = blockIdx.y;
    const int m0   = blockIdx.x * 128;

    const int wm = wid >> 1;          // 0..3  (32 rows)
    const int wn = wid & 1;           // 0..1  (64 cols)

    float acc[2][8][4];
#pragma unroll
    for (int mf = 0; mf < 2; mf++)
#pragma unroll
        for (int nf = 0; nf < 8; nf++)
#pragma unroll
            for (int q = 0; q < 4; q++) acc[mf][nf][q] = 0.f;

    // ldmatrix row/lane components
    const int a_row = wm * 32 + (lane & 15);                      // + mf*16
    const int a_ch  = lane >> 4;                                  // 0/1 (k16 half)
    const int b_row = wn * 64 + (lane & 7) + ((lane >> 4) << 3);  // + p*16
    const int b_ch  = (lane >> 3) & 1;

    const size_t bBase = (size_t)b * DOUT * DIN;

    for (int kc = 0; kc < 2; kc++) {
        // --- load 64-k chunk of all 4 arrays into swizzled smem ---
        // 1024 16B-chunks per array; 4 per thread.
        {
            const int kOff = kc * 64;
#pragma unroll
            for (int i = 0; i < 4; i++) {
                const int slot = tid * 4 + i;       // 0..1023
                const int row  = slot >> 3;         // 0..127
                const int c    = slot & 7;          // 16B chunk in row
                const uint32_t dst = (uint32_t)(row * 128 + ((c ^ (row & 7)) << 4));
                const size_t gx = (size_t)(m0 + row) * DIN + kOff + c * 8;
                const size_t gb = bBase + (size_t)row * DIN + kOff + c * 8;
                *(uint4*)(smem + S_XH + dst) = *(const uint4*)(g_Xh + gx);
                *(uint4*)(smem + S_XL + dst) = *(const uint4*)(g_Xl + gx);
                *(uint4*)(smem + S_BH + dst) = *(const uint4*)(g_BTh + gb);
                *(uint4*)(smem + S_BL + dst) = *(const uint4*)(g_BTl + gb);
            }
        }
        __syncthreads();

#pragma unroll
        for (int kf = 0; kf < 4; kf++) {
            uint Ah[2][4], Al[2][4];
#pragma unroll
            for (int mf = 0; mf < 2; mf++) {
                const int row = a_row + mf * 16;
                const uint32_t addr = (uint32_t)(row * 128 +
                    (((kf * 2 + a_ch) ^ (row & 7)) << 4));
                ldsm_x4(Ah[mf], sbase + S_XH + addr);
                ldsm_x4(Al[mf], sbase + S_XL + addr);
            }
            uint Bh[4][4], Bl[4][4];
#pragma unroll
            for (int p = 0; p < 4; p++) {
                const int row = b_row + p * 16;
                const uint32_t addr = (uint32_t)(row * 128 +
                    (((kf * 2 + b_ch) ^ (row & 7)) << 4));
                ldsm_x4(Bh[p], sbase + S_BH + addr);
                ldsm_x4(Bl[p], sbase + S_BL + addr);
            }
#pragma unroll
            for (int mf = 0; mf < 2; mf++)
#pragma unroll
                for (int p = 0; p < 4; p++) {
                    mma_bf16(acc[mf][2 * p],     Ah[mf], Bh[p][0], Bh[p][1]);
                    mma_bf16(acc[mf][2 * p],     Ah[mf], Bl[p][0], Bl[p][1]);
                    mma_bf16(acc[mf][2 * p],     Al[mf], Bh[p][0], Bh[p][1]);
                    mma_bf16(acc[mf][2 * p + 1], Ah[mf], Bh[p][2], Bh[p][3]);
                    mma_bf16(acc[mf][2 * p + 1], Ah[mf], Bl[p][2], Bl[p][3]);
                    mma_bf16(acc[mf][2 * p + 1], Al[mf], Bh[p][2], Bh[p][3]);
                }
        }
        __syncthreads();
    }

    // --- epilogue: write XB[b] fp32 ---
    float* outBase = g_XB + (size_t)b * N_NODES * DOUT;
    const int g = lane >> 2;
    const int t2 = (lane & 3) * 2;
#pragma unroll
    for (int mf = 0; mf < 2; mf++) {
        const int r0 = m0 + wm * 32 + mf * 16 + g;
#pragma unroll
        for (int nf = 0; nf < 8; nf++) {
            const int col = wn * 64 + nf * 8 + t2;
            if (r0 < N_NODES)
                *(float2*)(outBase + (size_t)r0 * DOUT + col) =
                    make_float2(acc[mf][nf][0], acc[mf][nf][1]);
            if (r0 + 8 < N_NODES)
                *(float2*)(outBase + (size_t)(r0 + 8) * DOUT + col) =
                    make_float2(acc[mf][nf][2], acc[mf][nf][3]);
        }
    }
}

// ---------------------------------------------------------------------------
// FW[r][n][d] = sum_b comp[r][b] * XB[b][n][d]
// ---------------------------------------------------------------------------
__global__ __launch_bounds__(256)
void combine_kernel(const float* __restrict__ comp) {
    __shared__ float cs[R_REL * B_BASES];
    if (threadIdx.x < R_REL * B_BASES) cs[threadIdx.x] = comp[threadIdx.x];
    __syncthreads();

    const int id = blockIdx.x * blockDim.x + threadIdx.x;
    if (id >= N_NODES * 32) return;
    const int n  = id >> 5;
    const int d4 = (id & 31) * 4;

    float4 xb[8];
#pragma unroll
    for (int b = 0; b < B_BASES; b++)
        xb[b] = __ldg((const float4*)(g_XB + ((size_t)b * N_NODES + n) * DOUT + d4));

#pragma unroll
    for (int r = 0; r < R_REL; r++) {
        float4 o = make_float4(0.f, 0.f, 0.f, 0.f);
#pragma unroll
        for (int b = 0; b < B_BASES; b++) {
            const float c = cs[r * B_BASES + b];
            o.x += c * xb[b].x;
            o.y += c * xb[b].y;
            o.z += c * xb[b].z;
            o.w += c * xb[b].w;
        }
        *(float4*)(g_FW + ((size_t)r * N_NODES + n) * DOUT + d4) = o;
    }
}

// ---------------------------------------------------------------------------
// Sorted scatter: one warp per output row; register accumulation; single
// non-atomic row write.
// ---------------------------------------------------------------------------
__global__ void __launch_bounds__(256)
scatter2_kernel(float* __restrict__ out) {
    const int warpId = (blockIdx.x * blockDim.x + threadIdx.x) >> 5;
    if (warpId >= N_NODES) return;
    const int lane = threadIdx.x & 31;

    const int s = g_start[warpId];
    const int e = g_start[warpId + 1];

    float4 acc = make_float4(0.f, 0.f, 0.f, 0.f);
    int i = s;
    for (; i + 4 <= e; i += 4) {
        int2 e0 = g_edge[i], e1 = g_edge[i + 1], e2 = g_edge[i + 2], e3 = g_edge[i + 3];
        float4 f0 = __ldg((const float4*)(g_FW + (size_t)e0.x * DOUT) + lane);
        float4 f1 = __ldg((const float4*)(g_FW + (size_t)e1.x * DOUT) + lane);
        float4 f2 = __ldg((const float4*)(g_FW + (size_t)e2.x * DOUT) + lane);
        float4 f3 = __ldg((const float4*)(g_FW + (size_t)e3.x * DOUT) + lane);
        const float v0 = __int_as_float(e0.y), v1 = __int_as_float(e1.y);
        const float v2 = __int_as_float(e2.y), v3 = __int_as_float(e3.y);
        acc.x += v0 * f0.x + v1 * f1.x + v2 * f2.x + v3 * f3.x;
        acc.y += v0 * f0.y + v1 * f1.y + v2 * f2.y + v3 * f3.y;
        acc.z += v0 * f0.z + v1 * f1.z + v2 * f2.z + v3 * f3.z;
        acc.w += v0 * f0.w + v1 * f1.w + v2 * f2.w + v3 * f3.w;
    }
    for (; i < e; i++) {
        int2 ed = g_edge[i];
        float4 f = __ldg((const float4*)(g_FW + (size_t)ed.x * DOUT) + lane);
        const float v = __int_as_float(ed.y);
        acc.x += v * f.x; acc.y += v * f.y; acc.z += v * f.z; acc.w += v * f.w;
    }
    *(float4*)(out + (size_t)warpId * DOUT + lane * 4) = acc;
}

// ---------------------------------------------------------------------------
extern "C" void kernel_launch(void* const* d_in, const int* in_sizes, int n_in,
                              void* d_out, int out_size) {
    const float* X      = (const float*)d_in[0];
    const void*  A_rows = d_in[1];
    const void*  A_cols = d_in[2];
    const float* A_vals = (const float*)d_in[3];
    const float* basis  = (const float*)d_in[4];
    const float* comp   = (const float*)d_in[5];
    float* out = (float*)d_out;

    cudaFuncSetAttribute(gemm_mma_kernel,
                         cudaFuncAttributeMaxDynamicSharedMemorySize, S_TOTAL);

    // Launch order chosen so gemm_mma_kernel is launch #4 (ncu -s 5 -c 1
    // lands there) while preserving dependencies.
    detect_dtype_kernel<<<1, 1>>>((const unsigned int*)A_rows);         // 1

    const int px = (N_PAD * DIN) / 8;
    prep_x_kernel<<<(px + 255) / 256, 256>>>(X);                        // 2
    const int pb = B_BASES * DOUT * (DIN / 4);
    prep_bt_kernel<<<(pb + 255) / 256, 256>>>(basis);                   // 3

    dim3 ggrid(M_TILES, B_BASES);
    gemm_mma_kernel<<<ggrid, 256, S_TOTAL>>>(0);                        // 4 (profiled)

    zero_cnt_kernel<<<(N_NODES + 255) / 256, 256>>>();                  // 5
    hist_kernel<<<(NNZ + 255) / 256, 256>>>(A_rows);                    // 6
    scan_kernel<<<1, 1024>>>();                                         // 7
    fill_kernel<<<(NNZ + 255) / 256, 256>>>(A_rows, A_cols, A_vals);    // 8

    const int cthreads = N_NODES * 32;
    combine_kernel<<<(cthreads + 255) / 256, 256>>>(comp);              // 9

    const long long sthreads = (long long)N_NODES * 32;
    scatter2_kernel<<<(unsigned)((sthreads + 255) / 256), 256>>>(out);  // 10
}